// round 1
// baseline (speedup 1.0000x reference)
#include <cuda_runtime.h>
#include <math.h>
#include <stdint.h>

#define N_MAX 100000
#define E_MAX 2400000

// ---- scratch (device globals; no allocation allowed) ----
// All big arrays declared as float4 to guarantee 16B alignment for red.v4 / LDG.128.
__device__ float4 g_h1_4 [N_MAX * 16];  // [N,64] pre-BN layer1
__device__ float4 g_h2_4 [N_MAX * 8];   // [N,32] pre-BN layer2
__device__ float4 g_emb_4[N_MAX * 8];   // [N,32] encoder output
__device__ float4 g_Ap_4 [N_MAX * 8];   // ppmi-agg of emb
__device__ float4 g_Aa_4 [N_MAX * 8];   // gcn-agg of emb
__device__ float4 g_fp_4 [N_MAX * 8];   // feature_p
__device__ float4 g_fa_4 [N_MAX * 8];   // feature_a
__device__ float4 g_Bp_4 [N_MAX * 8];   // ppmi-agg of feature_p
__device__ float4 g_Ba_4 [N_MAX * 8];   // gcn-agg of feature_a
__device__ float  g_degp [N_MAX];
__device__ float  g_dega [N_MAX];
__device__ float  g_dinvp[N_MAX];
__device__ float  g_dinva[N_MAX];
__device__ float  g_stat1[128];         // sum[64], sumsq[64]
__device__ float  g_stat2[64];          // sum[32], sumsq[32]
__device__ float  g_bn1  [128];         // scale[64], shift[64]
__device__ float  g_bn2  [64];          // scale[32], shift[32]

#define G_H1  ((float*)g_h1_4)
#define G_H2  ((float*)g_h2_4)
#define G_EMB ((float*)g_emb_4)
#define G_AP  ((float*)g_Ap_4)
#define G_AA  ((float*)g_Aa_4)
#define G_FP  ((float*)g_fp_4)
#define G_FA  ((float*)g_fa_4)
#define G_BP  ((float*)g_Bp_4)
#define G_BA  ((float*)g_Ba_4)

__device__ __forceinline__ float eluf(float v) {
    return v > 0.f ? v : (expf(v) - 1.f);
}

__device__ __forceinline__ float wsum32(float v) {
    #pragma unroll
    for (int o = 16; o; o >>= 1) v += __shfl_xor_sync(0xffffffffu, v, o);
    return v;
}

// vectorized fp32 reduction-add to global (sm_90+)
__device__ __forceinline__ void red4(float4* p, float a, float b, float c, float d) {
    asm volatile("red.global.add.v4.f32 [%0], {%1,%2,%3,%4};"
                 :: "l"(p), "f"(a), "f"(b), "f"(c), "f"(d) : "memory");
}

// ---------------------------------------------------------------------------
// K0: init (stats zero, degrees = self-loop weight 2.0)
// ---------------------------------------------------------------------------
__global__ void k_init(int n) {
    int i = blockIdx.x * blockDim.x + threadIdx.x;
    if (i < n) { g_degp[i] = 2.f; g_dega[i] = 2.f; }
    if (i < 128) g_stat1[i] = 0.f;
    if (i < 64)  g_stat2[i] = 0.f;
}

// K1: degree accumulation over edges (segment over row = src)
__global__ void k_deg(const int* __restrict__ src, const float* __restrict__ ppmi, int e) {
    int i = blockIdx.x * blockDim.x + threadIdx.x;
    if (i >= e) return;
    int s = src[i];
    atomicAdd(&g_dega[s], 1.f);
    atomicAdd(&g_degp[s], ppmi[i]);
}

// K2: deg^-0.5
__global__ void k_dinv(int n) {
    int i = blockIdx.x * blockDim.x + threadIdx.x;
    if (i >= n) return;
    g_dinvp[i] = rsqrtf(g_degp[i]);
    g_dinva[i] = rsqrtf(g_dega[i]);
}

// ---------------------------------------------------------------------------
// K3: h1 = x @ W1 + b1  (N x 256 x 64) + column stats.
// One warp computes 4 rows; lane owns 2 output cols. W1 served from L1.
// ---------------------------------------------------------------------------
__global__ void k_gemm1(const float* __restrict__ x, const float* __restrict__ W,
                        const float* __restrict__ b, int n) {
    int lane = threadIdx.x & 31;
    int gw   = (blockIdx.x * blockDim.x + threadIdx.x) >> 5;
    int nw   = (gridDim.x * blockDim.x) >> 5;
    int c0 = lane * 2;
    float bb0 = __ldg(b + c0), bb1 = __ldg(b + c0 + 1);
    float s0 = 0.f, s1 = 0.f, q0 = 0.f, q1 = 0.f;

    for (int r0 = gw * 4; r0 < n; r0 += nw * 4) {
        if (r0 + 3 < n) {
            float a00=0,a01=0,a10=0,a11=0,a20=0,a21=0,a30=0,a31=0;
            const float4* x0 = (const float4*)(x + (size_t)r0 * 256);
            const float4* x1 = (const float4*)(x + (size_t)(r0+1) * 256);
            const float4* x2 = (const float4*)(x + (size_t)(r0+2) * 256);
            const float4* x3 = (const float4*)(x + (size_t)(r0+3) * 256);
            #pragma unroll 4
            for (int k4 = 0; k4 < 64; k4++) {
                float4 v0 = __ldg(x0 + k4);
                float4 v1 = __ldg(x1 + k4);
                float4 v2 = __ldg(x2 + k4);
                float4 v3 = __ldg(x3 + k4);
                int kb = k4 * 4;
                #pragma unroll
                for (int t = 0; t < 4; t++) {
                    float2 w = __ldg((const float2*)(W + (kb + t) * 64 + c0));
                    float e0 = (t==0)?v0.x:(t==1)?v0.y:(t==2)?v0.z:v0.w;
                    float e1 = (t==0)?v1.x:(t==1)?v1.y:(t==2)?v1.z:v1.w;
                    float e2 = (t==0)?v2.x:(t==1)?v2.y:(t==2)?v2.z:v2.w;
                    float e3 = (t==0)?v3.x:(t==1)?v3.y:(t==2)?v3.z:v3.w;
                    a00 += e0*w.x; a01 += e0*w.y;
                    a10 += e1*w.x; a11 += e1*w.y;
                    a20 += e2*w.x; a21 += e2*w.y;
                    a30 += e3*w.x; a31 += e3*w.y;
                }
            }
            float v;
            v = a00 + bb0; s0 += v; q0 += v*v;
            float u = a01 + bb1; s1 += u; q1 += u*u;
            ((float2*)(G_H1 + (size_t)(r0  ) * 64))[lane] = make_float2(v, u);
            v = a10 + bb0; s0 += v; q0 += v*v;
            u = a11 + bb1; s1 += u; q1 += u*u;
            ((float2*)(G_H1 + (size_t)(r0+1) * 64))[lane] = make_float2(v, u);
            v = a20 + bb0; s0 += v; q0 += v*v;
            u = a21 + bb1; s1 += u; q1 += u*u;
            ((float2*)(G_H1 + (size_t)(r0+2) * 64))[lane] = make_float2(v, u);
            v = a30 + bb0; s0 += v; q0 += v*v;
            u = a31 + bb1; s1 += u; q1 += u*u;
            ((float2*)(G_H1 + (size_t)(r0+3) * 64))[lane] = make_float2(v, u);
        } else {
            for (int r = r0; r < n; r++) {
                float a0 = 0.f, a1 = 0.f;
                const float* xr = x + (size_t)r * 256;
                for (int k = 0; k < 256; k++) {
                    float2 w = __ldg((const float2*)(W + k * 64 + c0));
                    float xv = __ldg(xr + k);
                    a0 += xv * w.x; a1 += xv * w.y;
                }
                float v = a0 + bb0; s0 += v; q0 += v*v;
                float u = a1 + bb1; s1 += u; q1 += u*u;
                ((float2*)(G_H1 + (size_t)r * 64))[lane] = make_float2(v, u);
            }
        }
    }
    atomicAdd(&g_stat1[c0    ], s0);
    atomicAdd(&g_stat1[c0 + 1], s1);
    atomicAdd(&g_stat1[64 + c0    ], q0);
    atomicAdd(&g_stat1[64 + c0 + 1], q1);
}

// K4: finalize BN1 (scale/shift)
__global__ void k_bn1(const float* __restrict__ g, const float* __restrict__ be, int n) {
    int j = threadIdx.x;  // 64 threads
    float inv_n = 1.f / (float)n;
    float m = g_stat1[j] * inv_n;
    float v = g_stat1[64 + j] * inv_n - m * m;
    float a = __ldg(g + j) * rsqrtf(v + 1e-3f);
    g_bn1[j] = a;
    g_bn1[64 + j] = __ldg(be + j) - a * m;
}

// ---------------------------------------------------------------------------
// K5: emb1 = elu(bn1(h1)); h2 = emb1 @ W2 + b2 (warp per row, shuffle bcast)
// ---------------------------------------------------------------------------
__global__ void k_gemm2(const float* __restrict__ W2, const float* __restrict__ b2, int n) {
    int lane = threadIdx.x & 31;
    int gw   = (blockIdx.x * blockDim.x + threadIdx.x) >> 5;
    int nw   = (gridDim.x * blockDim.x) >> 5;
    float sa0 = g_bn1[lane],      sc0 = g_bn1[64 + lane];
    float sa1 = g_bn1[32 + lane], sc1 = g_bn1[96 + lane];
    float bias = __ldg(b2 + lane);
    float s = 0.f, q = 0.f;

    for (int r = gw; r < n; r += nw) {
        float h0 = G_H1[(size_t)r * 64 + lane];
        float h1 = G_H1[(size_t)r * 64 + 32 + lane];
        float e0 = eluf(sa0 * h0 + sc0);
        float e1 = eluf(sa1 * h1 + sc1);
        float acc = bias;
        #pragma unroll
        for (int j = 0; j < 32; j++) {
            float xv = __shfl_sync(0xffffffffu, e0, j);
            acc += xv * __ldg(W2 + j * 32 + lane);
        }
        #pragma unroll
        for (int j = 0; j < 32; j++) {
            float xv = __shfl_sync(0xffffffffu, e1, j);
            acc += xv * __ldg(W2 + (32 + j) * 32 + lane);
        }
        G_H2[(size_t)r * 32 + lane] = acc;
        s += acc; q += acc * acc;
    }
    atomicAdd(&g_stat2[lane], s);
    atomicAdd(&g_stat2[32 + lane], q);
}

// K6: finalize BN2
__global__ void k_bn2(const float* __restrict__ g, const float* __restrict__ be, int n) {
    int j = threadIdx.x;  // 32 threads
    float inv_n = 1.f / (float)n;
    float m = g_stat2[j] * inv_n;
    float v = g_stat2[32 + j] * inv_n - m * m;
    float a = __ldg(g + j) * rsqrtf(v + 1e-3f);
    g_bn2[j] = a;
    g_bn2[32 + j] = __ldg(be + j) - a * m;
}

// K7: emb = elu(bn2(h2)); init aggregations with self-loop term 2/deg * emb
__global__ void k_emb(int n) {
    int i = blockIdx.x * blockDim.x + threadIdx.x;
    if (i >= n * 32) return;
    int node = i >> 5, c = i & 31;
    float e = eluf(g_bn2[c] * G_H2[i] + g_bn2[32 + c]);
    G_EMB[i] = e;
    float dp = g_dinvp[node], da = g_dinva[node];
    G_AP[i] = 2.f * dp * dp * e;
    G_AA[i] = 2.f * da * da * e;
}

// ---------------------------------------------------------------------------
// K8: edge scatter pass 1: Ap[dst] += np*emb[src]; Aa[dst] += ng*emb[src]
// ---------------------------------------------------------------------------
__global__ void k_scat1(const int* __restrict__ src, const int* __restrict__ dst,
                        const float* __restrict__ ppmi, int e) {
    int i = blockIdx.x * blockDim.x + threadIdx.x;
    if (i >= e) return;
    int s = src[i], d = dst[i];
    float np = __ldg(&g_dinvp[s]) * __ldg(ppmi + i) * __ldg(&g_dinvp[d]);
    float ng = __ldg(&g_dinva[s]) * __ldg(&g_dinva[d]);
    const float4* ev = g_emb_4 + (size_t)s * 8;
    float4* ap = g_Ap_4 + (size_t)d * 8;
    float4* aa = g_Aa_4 + (size_t)d * 8;
    #pragma unroll
    for (int j = 0; j < 8; j++) {
        float4 v = __ldg(ev + j);
        red4(ap + j, np * v.x, np * v.y, np * v.z, np * v.w);
        red4(aa + j, ng * v.x, ng * v.y, ng * v.z, ng * v.w);
    }
}

// K9: feature = relu(Agg @ Wg1 + bg1); init B with self-loop term
__global__ void k_feat(const float* __restrict__ Wg1, const float* __restrict__ bg1, int n) {
    int lane = threadIdx.x & 31;
    int gw   = (blockIdx.x * blockDim.x + threadIdx.x) >> 5;
    int nw   = (gridDim.x * blockDim.x) >> 5;
    float bias = __ldg(bg1 + lane);
    for (int r = gw; r < n; r += nw) {
        float ap = G_AP[(size_t)r * 32 + lane];
        float aa = G_AA[(size_t)r * 32 + lane];
        float accp = bias, acca = bias;
        #pragma unroll
        for (int j = 0; j < 32; j++) {
            float w  = __ldg(Wg1 + j * 32 + lane);
            accp += __shfl_sync(0xffffffffu, ap, j) * w;
            acca += __shfl_sync(0xffffffffu, aa, j) * w;
        }
        float fp = fmaxf(accp, 0.f), fa = fmaxf(acca, 0.f);
        G_FP[(size_t)r * 32 + lane] = fp;
        G_FA[(size_t)r * 32 + lane] = fa;
        float dp = g_dinvp[r], da = g_dinva[r];
        G_BP[(size_t)r * 32 + lane] = 2.f * dp * dp * fp;
        G_BA[(size_t)r * 32 + lane] = 2.f * da * da * fa;
    }
}

// K10: edge scatter pass 2: Bp[dst] += np*fp[src]; Ba[dst] += ng*fa[src]
__global__ void k_scat2(const int* __restrict__ src, const int* __restrict__ dst,
                        const float* __restrict__ ppmi, int e) {
    int i = blockIdx.x * blockDim.x + threadIdx.x;
    if (i >= e) return;
    int s = src[i], d = dst[i];
    float np = __ldg(&g_dinvp[s]) * __ldg(ppmi + i) * __ldg(&g_dinvp[d]);
    float ng = __ldg(&g_dinva[s]) * __ldg(&g_dinva[d]);
    const float4* fp = g_fp_4 + (size_t)s * 8;
    const float4* fa = g_fa_4 + (size_t)s * 8;
    float4* bp = g_Bp_4 + (size_t)d * 8;
    float4* ba = g_Ba_4 + (size_t)d * 8;
    #pragma unroll
    for (int j = 0; j < 8; j++) {
        float4 vp = __ldg(fp + j);
        float4 va = __ldg(fa + j);
        red4(bp + j, np * vp.x, np * vp.y, np * vp.z, np * vp.w);
        red4(ba + j, ng * va.x, ng * va.y, ng * va.z, ng * va.w);
    }
}

// ---------------------------------------------------------------------------
// K11: mu/logvar matvecs, reparameterize, attention, write output (warp/row)
// ---------------------------------------------------------------------------
__global__ void k_final(const float* __restrict__ Wg2, const float* __restrict__ bg2,
                        const float* __restrict__ Wg3, const float* __restrict__ bg3,
                        const float* __restrict__ Watt, const float* __restrict__ batt,
                        const float* __restrict__ noise_p, const float* __restrict__ noise_a,
                        float* __restrict__ out, int n) {
    int lane = threadIdx.x & 31;
    int gw   = (blockIdx.x * blockDim.x + threadIdx.x) >> 5;
    int nw   = (gridDim.x * blockDim.x) >> 5;
    float b2 = __ldg(bg2 + lane), b3 = __ldg(bg3 + lane);
    float wa = __ldg(Watt + lane), bt = __ldg(batt);

    for (int r = gw; r < n; r += nw) {
        float bp = G_BP[(size_t)r * 32 + lane];
        float ba = G_BA[(size_t)r * 32 + lane];
        float mup = b2, lvp = b3, mua = b2, lva = b3;
        #pragma unroll
        for (int j = 0; j < 32; j++) {
            float xp = __shfl_sync(0xffffffffu, bp, j);
            float xa = __shfl_sync(0xffffffffu, ba, j);
            float w2 = __ldg(Wg2 + j * 32 + lane);
            float w3 = __ldg(Wg3 + j * 32 + lane);
            mup += xp * w2; lvp += xp * w3;
            mua += xa * w2; lva += xa * w3;
        }
        float zp = noise_p[(size_t)r * 32 + lane] * expf(lvp) + mup;
        float za = noise_a[(size_t)r * 32 + lane] * expf(lva) + mua;
        float fp = G_FP[(size_t)r * 32 + lane];
        float fa = G_FA[(size_t)r * 32 + lane];

        // attention over {fp, fa}
        float d1 = wsum32(fp * wa) + bt;
        float d2 = wsum32(fa * wa) + bt;
        float m = fmaxf(d1, d2);
        float w1 = expf(d1 - m), w2e = expf(d2 - m);
        float inv = 1.f / (w1 + w2e);
        out[(size_t)r * 64 + lane] = (w1 * fp + w2e * fa) * inv;

        // attention over {zp, za}
        d1 = wsum32(zp * wa) + bt;
        d2 = wsum32(za * wa) + bt;
        m = fmaxf(d1, d2);
        w1 = expf(d1 - m); w2e = expf(d2 - m);
        inv = 1.f / (w1 + w2e);
        out[(size_t)r * 64 + 32 + lane] = (w1 * zp + w2e * za) * inv;
    }
}

// ---------------------------------------------------------------------------
extern "C" void kernel_launch(void* const* d_in, const int* in_sizes, int n_in,
                              void* d_out, int out_size) {
    const float* x      = (const float*)d_in[0];
    const int*   ei     = (const int*)  d_in[1];
    const float* ppmi   = (const float*)d_in[2];
    const float* noisep = (const float*)d_in[3];
    const float* noisea = (const float*)d_in[4];
    const float* W1   = (const float*)d_in[5];
    const float* b1   = (const float*)d_in[6];
    const float* g1   = (const float*)d_in[7];
    const float* be1  = (const float*)d_in[8];
    const float* W2   = (const float*)d_in[9];
    const float* b2   = (const float*)d_in[10];
    const float* g2   = (const float*)d_in[11];
    const float* be2  = (const float*)d_in[12];
    const float* Wg1  = (const float*)d_in[13];
    const float* bg1  = (const float*)d_in[14];
    const float* Wg2  = (const float*)d_in[15];
    const float* bg2  = (const float*)d_in[16];
    const float* Wg3  = (const float*)d_in[17];
    const float* bg3  = (const float*)d_in[18];
    const float* Watt = (const float*)d_in[19];
    const float* batt = (const float*)d_in[20];
    float* out = (float*)d_out;

    int n = in_sizes[0] / 256;   // 100000
    int e = in_sizes[2];         // 2400000
    const int* src = ei;
    const int* dst = ei + e;

    int nb = (n + 255) / 256;
    int eb = (e + 255) / 256;

    k_init<<<nb, 256>>>(n);
    k_deg <<<eb, 256>>>(src, ppmi, e);
    k_dinv<<<nb, 256>>>(n);
    k_gemm1<<<1184, 256>>>(x, W1, b1, n);
    k_bn1<<<1, 64>>>(g1, be1, n);
    k_gemm2<<<1184, 256>>>(W2, b2, n);
    k_bn2<<<1, 32>>>(g2, be2, n);
    k_emb<<<(n * 32 + 255) / 256, 256>>>(n);
    k_scat1<<<eb, 256>>>(src, dst, ppmi, e);
    k_feat<<<1184, 256>>>(Wg1, bg1, n);
    k_scat2<<<eb, 256>>>(src, dst, ppmi, e);
    k_final<<<1184, 256>>>(Wg2, bg2, Wg3, bg3, Watt, batt, noisep, noisea, out, n);
}

// round 11
// speedup vs baseline: 2.1375x; 2.1375x over previous
#include <cuda_runtime.h>
#include <math.h>
#include <stdint.h>

#define N_MAX 100000
#define E_MAX 2400000

// ---- scratch (device globals; no allocation allowed) ----
__device__ float4 g_h1_4 [N_MAX * 16];  // [N,64] pre-BN layer1
__device__ float4 g_h2_4 [N_MAX * 8];   // [N,32] pre-BN layer2
__device__ float4 g_emb_4[N_MAX * 8];   // [N,32] encoder output
__device__ float4 g_fp_4 [N_MAX * 8];   // feature_p
__device__ float4 g_fa_4 [N_MAX * 8];   // feature_a
__device__ float  g_degp [N_MAX];
__device__ float  g_dega [N_MAX];
__device__ float  g_dinvp[N_MAX];
__device__ float  g_dinva[N_MAX];
__device__ float  g_stat1[128];         // sum[64], sumsq[64]
__device__ float  g_stat2[64];          // sum[32], sumsq[32]
__device__ float  g_bn1  [128];         // scale[64], shift[64]
__device__ float  g_bn2  [64];          // scale[32], shift[32]
// CSR (bucketed by dst) rebuilt every launch
__device__ int    g_cnt   [N_MAX];
__device__ int    g_scan  [N_MAX];
__device__ int    g_blksum [128];
__device__ int    g_blkincl[128];
__device__ int    g_off   [N_MAX];
__device__ int    g_cursor[N_MAX];
__device__ int    g_ssrc  [E_MAX];
__device__ float2 g_wsort [E_MAX];      // (np, ng) per bucketed edge

#define G_H1  ((float*)g_h1_4)
#define G_H2  ((float*)g_h2_4)
#define G_EMB ((float*)g_emb_4)
#define G_FP  ((float*)g_fp_4)
#define G_FA  ((float*)g_fa_4)

__device__ __forceinline__ float eluf(float v) {
    return v > 0.f ? v : (expf(v) - 1.f);
}

__device__ __forceinline__ float wsum32(float v) {
    #pragma unroll
    for (int o = 16; o; o >>= 1) v += __shfl_xor_sync(0xffffffffu, v, o);
    return v;
}

// ---------------------------------------------------------------------------
// K0: init (stats zero, degrees = self-loop weight 2.0, histogram zero)
// ---------------------------------------------------------------------------
__global__ void k_init(int n) {
    int i = blockIdx.x * blockDim.x + threadIdx.x;
    if (i < n) { g_degp[i] = 2.f; g_dega[i] = 2.f; g_cnt[i] = 0; }
    if (i < 128) g_stat1[i] = 0.f;
    if (i < 64)  g_stat2[i] = 0.f;
}

// K1: degree accumulation (over src) + dst histogram for CSR
__global__ void k_deg(const int* __restrict__ src, const int* __restrict__ dst,
                      const float* __restrict__ ppmi, int e) {
    int i = blockIdx.x * blockDim.x + threadIdx.x;
    if (i >= e) return;
    int s = src[i];
    atomicAdd(&g_dega[s], 1.f);
    atomicAdd(&g_degp[s], ppmi[i]);
    atomicAdd(&g_cnt[dst[i]], 1);
}

// K2: deg^-0.5
__global__ void k_dinv(int n) {
    int i = blockIdx.x * blockDim.x + threadIdx.x;
    if (i >= n) return;
    g_dinvp[i] = rsqrtf(g_degp[i]);
    g_dinva[i] = rsqrtf(g_dega[i]);
}

// ---------------------------------------------------------------------------
// Scan: hierarchical inclusive scan of g_cnt -> exclusive offsets g_off
// ---------------------------------------------------------------------------
__global__ void k_scan_blk(int n) {   // grid = ceil(n/1024), block = 1024
    __shared__ int wsum[32];
    int tid = threadIdx.x;
    int i = blockIdx.x * 1024 + tid;
    int lane = tid & 31, wid = tid >> 5;
    int x = (i < n) ? g_cnt[i] : 0;
    #pragma unroll
    for (int o = 1; o < 32; o <<= 1) {
        int t = __shfl_up_sync(0xffffffffu, x, o);
        if (lane >= o) x += t;
    }
    if (lane == 31) wsum[wid] = x;
    __syncthreads();
    if (wid == 0) {
        int y = wsum[lane];
        #pragma unroll
        for (int o = 1; o < 32; o <<= 1) {
            int t = __shfl_up_sync(0xffffffffu, y, o);
            if (lane >= o) y += t;
        }
        wsum[lane] = y;
    }
    __syncthreads();
    int incl = x + (wid ? wsum[wid - 1] : 0);
    if (i < n) g_scan[i] = incl;
    if (tid == 1023) g_blksum[blockIdx.x] = incl;
}

__global__ void k_scan_top(int nb) {  // 1 block, 128 threads (nb <= 128)
    __shared__ int ws[4];
    int tid = threadIdx.x, lane = tid & 31, wid = tid >> 5;
    int x = (tid < nb) ? g_blksum[tid] : 0;
    #pragma unroll
    for (int o = 1; o < 32; o <<= 1) {
        int t = __shfl_up_sync(0xffffffffu, x, o);
        if (lane >= o) x += t;
    }
    if (lane == 31) ws[wid] = x;
    __syncthreads();
    int base = 0;
    for (int k = 0; k < wid; k++) base += ws[k];
    if (tid < nb) g_blkincl[tid] = x + base;
}

__global__ void k_csr_off(int n) {
    int i = blockIdx.x * blockDim.x + threadIdx.x;
    if (i >= n) return;
    int b = i >> 10;
    int off = g_scan[i] - g_cnt[i] + (b ? g_blkincl[b - 1] : 0);
    g_off[i] = off;
    g_cursor[i] = off;
}

// K fill: bucket edges by dst, precompute both norms per edge
__global__ void k_fill(const int* __restrict__ src, const int* __restrict__ dst,
                       const float* __restrict__ ppmi, int e) {
    int i = blockIdx.x * blockDim.x + threadIdx.x;
    if (i >= e) return;
    int s = src[i], d = dst[i];
    int pos = atomicAdd(&g_cursor[d], 1);
    float np = __ldg(&g_dinvp[s]) * __ldg(ppmi + i) * __ldg(&g_dinvp[d]);
    float ng = __ldg(&g_dinva[s]) * __ldg(&g_dinva[d]);
    g_ssrc[pos] = s;
    g_wsort[pos] = make_float2(np, ng);
}

// ---------------------------------------------------------------------------
// K3: h1 = x @ W1 + b1 (N x 256 x 64), smem-staged x, block-reduced stats.
// Block = 256 threads, 8 warps, each warp computes 4 rows, lane owns 2 cols.
// ---------------------------------------------------------------------------
__global__ void __launch_bounds__(256) k_gemm1(
        const float* __restrict__ x, const float* __restrict__ W,
        const float* __restrict__ b, int n) {
    __shared__ float4 sx[2048];   // 32 rows x 256 floats = 32KB
    __shared__ float rs[64], rq[64];
    int tid = threadIdx.x;
    if (tid < 64) { rs[tid] = 0.f; rq[tid] = 0.f; }

    int r0 = blockIdx.x * 32;
    int rows = n - r0; if (rows > 32) rows = 32;
    const float4* xg = (const float4*)(x + (size_t)r0 * 256);
    #pragma unroll
    for (int t = 0; t < 8; t++) {
        int idx = tid + t * 256;
        sx[idx] = (idx < rows * 64) ? __ldg(xg + idx) : make_float4(0.f, 0.f, 0.f, 0.f);
    }
    __syncthreads();

    int warp = tid >> 5, lane = tid & 31, c0 = lane * 2;
    int rr = warp * 4;
    float bb0 = __ldg(b + c0), bb1 = __ldg(b + c0 + 1);
    float a00 = 0.f, a01 = 0.f, a10 = 0.f, a11 = 0.f;
    float a20 = 0.f, a21 = 0.f, a30 = 0.f, a31 = 0.f;

    #pragma unroll 4
    for (int k4 = 0; k4 < 64; k4++) {
        float4 v0 = sx[(rr + 0) * 64 + k4];
        float4 v1 = sx[(rr + 1) * 64 + k4];
        float4 v2 = sx[(rr + 2) * 64 + k4];
        float4 v3 = sx[(rr + 3) * 64 + k4];
        int kb = k4 * 4;
        #pragma unroll
        for (int t = 0; t < 4; t++) {
            float2 w = __ldg((const float2*)(W + (kb + t) * 64 + c0));
            float e0 = (t == 0) ? v0.x : (t == 1) ? v0.y : (t == 2) ? v0.z : v0.w;
            float e1 = (t == 0) ? v1.x : (t == 1) ? v1.y : (t == 2) ? v1.z : v1.w;
            float e2 = (t == 0) ? v2.x : (t == 1) ? v2.y : (t == 2) ? v2.z : v2.w;
            float e3 = (t == 0) ? v3.x : (t == 1) ? v3.y : (t == 2) ? v3.z : v3.w;
            a00 += e0 * w.x; a01 += e0 * w.y;
            a10 += e1 * w.x; a11 += e1 * w.y;
            a20 += e2 * w.x; a21 += e2 * w.y;
            a30 += e3 * w.x; a31 += e3 * w.y;
        }
    }

    float s0 = 0.f, s1 = 0.f, q0 = 0.f, q1 = 0.f;
    float av[4][2] = {{a00, a01}, {a10, a11}, {a20, a21}, {a30, a31}};
    #pragma unroll
    for (int i = 0; i < 4; i++) {
        int r = r0 + rr + i;
        if (r < n) {
            float v = av[i][0] + bb0;
            float u = av[i][1] + bb1;
            s0 += v; q0 += v * v;
            s1 += u; q1 += u * u;
            ((float2*)(G_H1 + (size_t)r * 64))[lane] = make_float2(v, u);
        }
    }
    atomicAdd(&rs[c0], s0);
    atomicAdd(&rs[c0 + 1], s1);
    atomicAdd(&rq[c0], q0);
    atomicAdd(&rq[c0 + 1], q1);
    __syncthreads();
    if (tid < 64) {
        atomicAdd(&g_stat1[tid], rs[tid]);
        atomicAdd(&g_stat1[64 + tid], rq[tid]);
    }
}

// K4: finalize BN1
__global__ void k_bn1(const float* __restrict__ g, const float* __restrict__ be, int n) {
    int j = threadIdx.x;  // 64 threads
    float inv_n = 1.f / (float)n;
    float m = g_stat1[j] * inv_n;
    float v = g_stat1[64 + j] * inv_n - m * m;
    float a = __ldg(g + j) * rsqrtf(v + 1e-3f);
    g_bn1[j] = a;
    g_bn1[64 + j] = __ldg(be + j) - a * m;
}

// ---------------------------------------------------------------------------
// K5: emb1 = elu(bn1(h1)); h2 = emb1 @ W2 + b2 (warp per row)
// ---------------------------------------------------------------------------
__global__ void k_gemm2(const float* __restrict__ W2, const float* __restrict__ b2, int n) {
    __shared__ float rs[32], rq[32];
    int tid = threadIdx.x;
    if (tid < 32) { rs[tid] = 0.f; rq[tid] = 0.f; }
    __syncthreads();
    int lane = tid & 31;
    int gw = (blockIdx.x * blockDim.x + tid) >> 5;
    int nw = (gridDim.x * blockDim.x) >> 5;
    float sa0 = g_bn1[lane],      sc0 = g_bn1[64 + lane];
    float sa1 = g_bn1[32 + lane], sc1 = g_bn1[96 + lane];
    float bias = __ldg(b2 + lane);
    float s = 0.f, q = 0.f;

    for (int r = gw; r < n; r += nw) {
        float h0 = G_H1[(size_t)r * 64 + lane];
        float h1 = G_H1[(size_t)r * 64 + 32 + lane];
        float e0 = eluf(sa0 * h0 + sc0);
        float e1 = eluf(sa1 * h1 + sc1);
        float acc = bias;
        #pragma unroll
        for (int j = 0; j < 32; j++) {
            acc = fmaf(__shfl_sync(0xffffffffu, e0, j), __ldg(W2 + j * 32 + lane), acc);
        }
        #pragma unroll
        for (int j = 0; j < 32; j++) {
            acc = fmaf(__shfl_sync(0xffffffffu, e1, j), __ldg(W2 + (32 + j) * 32 + lane), acc);
        }
        G_H2[(size_t)r * 32 + lane] = acc;
        s += acc; q += acc * acc;
    }
    atomicAdd(&rs[lane], s);
    atomicAdd(&rq[lane], q);
    __syncthreads();
    if (tid < 32) {
        atomicAdd(&g_stat2[tid], rs[tid]);
        atomicAdd(&g_stat2[32 + tid], rq[tid]);
    }
}

// K6: finalize BN2
__global__ void k_bn2(const float* __restrict__ g, const float* __restrict__ be, int n) {
    int j = threadIdx.x;  // 32 threads
    float inv_n = 1.f / (float)n;
    float m = g_stat2[j] * inv_n;
    float v = g_stat2[32 + j] * inv_n - m * m;
    float a = __ldg(g + j) * rsqrtf(v + 1e-3f);
    g_bn2[j] = a;
    g_bn2[32 + j] = __ldg(be + j) - a * m;
}

// K7: emb = elu(bn2(h2))
__global__ void k_emb(int n) {
    int i = blockIdx.x * blockDim.x + threadIdx.x;
    if (i >= n * 32) return;
    int c = i & 31;
    G_EMB[i] = eluf(g_bn2[c] * G_H2[i] + g_bn2[32 + c]);
}

// ---------------------------------------------------------------------------
// Pass 1: warp per node. Gather both aggregations of emb via CSR, then
// feature = relu(Agg @ Wg1 + bg1). Atomic-free.
// ---------------------------------------------------------------------------
__global__ void k_pass1(const float* __restrict__ Wg1, const float* __restrict__ bg1, int n) {
    int gt = blockIdx.x * blockDim.x + threadIdx.x;
    int r = gt >> 5;
    if (r >= n) return;
    int lane = gt & 31;
    float dp = g_dinvp[r], da = g_dinva[r];
    float ev = G_EMB[(size_t)r * 32 + lane];
    float accp = 2.f * dp * dp * ev;
    float acca = 2.f * da * da * ev;
    int off = g_off[r], end = off + g_cnt[r];
    int j = off;
    for (; j + 4 <= end; j += 4) {
        int s0 = __ldg(g_ssrc + j),     s1 = __ldg(g_ssrc + j + 1);
        int s2 = __ldg(g_ssrc + j + 2), s3 = __ldg(g_ssrc + j + 3);
        float2 w0 = __ldg(g_wsort + j),     w1 = __ldg(g_wsort + j + 1);
        float2 w2 = __ldg(g_wsort + j + 2), w3 = __ldg(g_wsort + j + 3);
        float v0 = __ldg(&G_EMB[(size_t)s0 * 32 + lane]);
        float v1 = __ldg(&G_EMB[(size_t)s1 * 32 + lane]);
        float v2 = __ldg(&G_EMB[(size_t)s2 * 32 + lane]);
        float v3 = __ldg(&G_EMB[(size_t)s3 * 32 + lane]);
        accp = fmaf(w0.x, v0, accp); acca = fmaf(w0.y, v0, acca);
        accp = fmaf(w1.x, v1, accp); acca = fmaf(w1.y, v1, acca);
        accp = fmaf(w2.x, v2, accp); acca = fmaf(w2.y, v2, acca);
        accp = fmaf(w3.x, v3, accp); acca = fmaf(w3.y, v3, acca);
    }
    for (; j < end; j++) {
        int s = __ldg(g_ssrc + j);
        float2 w = __ldg(g_wsort + j);
        float v = __ldg(&G_EMB[(size_t)s * 32 + lane]);
        accp = fmaf(w.x, v, accp);
        acca = fmaf(w.y, v, acca);
    }
    float bias = __ldg(bg1 + lane);
    float accP = bias, accA = bias;
    #pragma unroll
    for (int t = 0; t < 32; t++) {
        float w = __ldg(Wg1 + t * 32 + lane);
        accP = fmaf(__shfl_sync(0xffffffffu, accp, t), w, accP);
        accA = fmaf(__shfl_sync(0xffffffffu, acca, t), w, accA);
    }
    G_FP[(size_t)r * 32 + lane] = fmaxf(accP, 0.f);
    G_FA[(size_t)r * 32 + lane] = fmaxf(accA, 0.f);
}

// ---------------------------------------------------------------------------
// Pass 2: warp per node. Gather aggregations of fp (ppmi) and fa (gcn),
// matvec Wg2/Wg3, reparameterize, attention, write output. Atomic-free.
// ---------------------------------------------------------------------------
__global__ void k_pass2(const float* __restrict__ Wg2, const float* __restrict__ bg2,
                        const float* __restrict__ Wg3, const float* __restrict__ bg3,
                        const float* __restrict__ Watt, const float* __restrict__ batt,
                        const float* __restrict__ noise_p, const float* __restrict__ noise_a,
                        float* __restrict__ out, int n) {
    int gt = blockIdx.x * blockDim.x + threadIdx.x;
    int r = gt >> 5;
    if (r >= n) return;
    int lane = gt & 31;
    float dp = g_dinvp[r], da = g_dinva[r];
    float fp = G_FP[(size_t)r * 32 + lane];
    float fa = G_FA[(size_t)r * 32 + lane];
    float accp = 2.f * dp * dp * fp;
    float acca = 2.f * da * da * fa;
    int off = g_off[r], end = off + g_cnt[r];
    int j = off;
    for (; j + 4 <= end; j += 4) {
        int s0 = __ldg(g_ssrc + j),     s1 = __ldg(g_ssrc + j + 1);
        int s2 = __ldg(g_ssrc + j + 2), s3 = __ldg(g_ssrc + j + 3);
        float2 w0 = __ldg(g_wsort + j),     w1 = __ldg(g_wsort + j + 1);
        float2 w2 = __ldg(g_wsort + j + 2), w3 = __ldg(g_wsort + j + 3);
        float p0 = __ldg(&G_FP[(size_t)s0 * 32 + lane]);
        float p1 = __ldg(&G_FP[(size_t)s1 * 32 + lane]);
        float p2 = __ldg(&G_FP[(size_t)s2 * 32 + lane]);
        float p3 = __ldg(&G_FP[(size_t)s3 * 32 + lane]);
        float a0 = __ldg(&G_FA[(size_t)s0 * 32 + lane]);
        float a1 = __ldg(&G_FA[(size_t)s1 * 32 + lane]);
        float a2 = __ldg(&G_FA[(size_t)s2 * 32 + lane]);
        float a3 = __ldg(&G_FA[(size_t)s3 * 32 + lane]);
        accp = fmaf(w0.x, p0, accp); acca = fmaf(w0.y, a0, acca);
        accp = fmaf(w1.x, p1, accp); acca = fmaf(w1.y, a1, acca);
        accp = fmaf(w2.x, p2, accp); acca = fmaf(w2.y, a2, acca);
        accp = fmaf(w3.x, p3, accp); acca = fmaf(w3.y, a3, acca);
    }
    for (; j < end; j++) {
        int s = __ldg(g_ssrc + j);
        float2 w = __ldg(g_wsort + j);
        accp = fmaf(w.x, __ldg(&G_FP[(size_t)s * 32 + lane]), accp);
        acca = fmaf(w.y, __ldg(&G_FA[(size_t)s * 32 + lane]), acca);
    }

    float b2 = __ldg(bg2 + lane), b3 = __ldg(bg3 + lane);
    float mup = b2, lvp = b3, mua = b2, lva = b3;
    #pragma unroll
    for (int t = 0; t < 32; t++) {
        float xp = __shfl_sync(0xffffffffu, accp, t);
        float xa = __shfl_sync(0xffffffffu, acca, t);
        float w2 = __ldg(Wg2 + t * 32 + lane);
        float w3 = __ldg(Wg3 + t * 32 + lane);
        mup = fmaf(xp, w2, mup); lvp = fmaf(xp, w3, lvp);
        mua = fmaf(xa, w2, mua); lva = fmaf(xa, w3, lva);
    }
    float zp = noise_p[(size_t)r * 32 + lane] * expf(lvp) + mup;
    float za = noise_a[(size_t)r * 32 + lane] * expf(lva) + mua;

    float wa = __ldg(Watt + lane), bt = __ldg(batt);

    // attention over {fp, fa}
    float d1 = wsum32(fp * wa) + bt;
    float d2 = wsum32(fa * wa) + bt;
    float m = fmaxf(d1, d2);
    float w1 = expf(d1 - m), w2e = expf(d2 - m);
    float inv = 1.f / (w1 + w2e);
    out[(size_t)r * 64 + lane] = (w1 * fp + w2e * fa) * inv;

    // attention over {zp, za}
    d1 = wsum32(zp * wa) + bt;
    d2 = wsum32(za * wa) + bt;
    m = fmaxf(d1, d2);
    w1 = expf(d1 - m); w2e = expf(d2 - m);
    inv = 1.f / (w1 + w2e);
    out[(size_t)r * 64 + 32 + lane] = (w1 * zp + w2e * za) * inv;
}

// ---------------------------------------------------------------------------
extern "C" void kernel_launch(void* const* d_in, const int* in_sizes, int n_in,
                              void* d_out, int out_size) {
    const float* x      = (const float*)d_in[0];
    const int*   ei     = (const int*)  d_in[1];
    const float* ppmi   = (const float*)d_in[2];
    const float* noisep = (const float*)d_in[3];
    const float* noisea = (const float*)d_in[4];
    const float* W1   = (const float*)d_in[5];
    const float* b1   = (const float*)d_in[6];
    const float* g1   = (const float*)d_in[7];
    const float* be1  = (const float*)d_in[8];
    const float* W2   = (const float*)d_in[9];
    const float* b2   = (const float*)d_in[10];
    const float* g2   = (const float*)d_in[11];
    const float* be2  = (const float*)d_in[12];
    const float* Wg1  = (const float*)d_in[13];
    const float* bg1  = (const float*)d_in[14];
    const float* Wg2  = (const float*)d_in[15];
    const float* bg2  = (const float*)d_in[16];
    const float* Wg3  = (const float*)d_in[17];
    const float* bg3  = (const float*)d_in[18];
    const float* Watt = (const float*)d_in[19];
    const float* batt = (const float*)d_in[20];
    float* out = (float*)d_out;

    int n = in_sizes[0] / 256;   // 100000
    int e = in_sizes[2];         // 2400000
    const int* src = ei;
    const int* dst = ei + e;

    int nb = (n + 255) / 256;
    int eb = (e + 255) / 256;
    int sb = (n + 1023) / 1024;
    int wb = (n * 32 + 255) / 256;

    k_init    <<<nb, 256>>>(n);
    k_deg     <<<eb, 256>>>(src, dst, ppmi, e);
    k_dinv    <<<nb, 256>>>(n);
    k_scan_blk<<<sb, 1024>>>(n);
    k_scan_top<<<1, 128>>>(sb);
    k_csr_off <<<nb, 256>>>(n);
    k_fill    <<<eb, 256>>>(src, dst, ppmi, e);
    k_gemm1   <<<(n + 31) / 32, 256>>>(x, W1, b1, n);
    k_bn1     <<<1, 64>>>(g1, be1, n);
    k_gemm2   <<<1184, 256>>>(W2, b2, n);
    k_bn2     <<<1, 32>>>(g2, be2, n);
    k_emb     <<<wb, 256>>>(n);
    k_pass1   <<<wb, 256>>>(Wg1, bg1, n);
    k_pass2   <<<wb, 256>>>(Wg2, bg2, Wg3, bg3, Watt, batt, noisep, noisea, out, n);
}